// round 1
// baseline (speedup 1.0000x reference)
#include <cuda_runtime.h>
#include <math.h>

#define BE 64
#define NOCT 32
#define NSAMP 32768
#define TPB 256
#define SAMP_PER_BLK 1024   // 4 samples per thread
#define NCHUNK (NSAMP / SAMP_PER_BLK)  // 32

// Scratch in device globals (no allocation allowed)
__device__ float    g_f0s[BE * NOCT];
__device__ float    g_amp[BE * NOCT];
__device__ int      g_nact[BE];
__device__ unsigned g_max[BE];

// ---------------------------------------------------------------------------
// Kernel 1: per-(b,e) parameter setup. Replicates the reference's f32
// rounding on the PHASE-critical path exactly (no FMA contraction, sequential
// cumsum) because phase errors amplify by t (up to 32768).
// ---------------------------------------------------------------------------
__global__ void setup_kernel(const float* __restrict__ f0_in,
                             const float* __restrict__ dec_in,
                             const float* __restrict__ sp_in) {
    int be = threadIdx.x;
    if (be >= BE) return;
    g_max[be] = 0u;

    const float MINF   = (float)(20.0 / 11025.0);
    const float FRANGE = (float)(3000.0 / 11025.0 - 20.0 / 11025.0);
    const float PI_F   = (float)3.14159265358979323846;
    const float RESF   = (float)((1.0 - 0.01) * 0.99);   // 0.9801

    float f0 = fabsf(f0_in[be]);
    // (min_freq + f0 * freq_range) * pi  -- separate RN ops, matching XLA
    float fsc = __fmul_rn(__fadd_rn(MINF, __fmul_rn(f0, FRANGE)), PI_F);
    float sp  = sp_in[be];

    // double sigmoid -> d -> log(d + 1e-12)
    float x  = dec_in[be];
    float s1 = 1.0f / (1.0f + expf(-x));
    float s2 = 1.0f / (1.0f + expf(-s1));
    float d  = __fadd_rn(0.01f, __fmul_rn(s2, RESF));
    float ld = logf(__fadd_rn(d, 1e-12f));

    float fac = 0.0f;  // cumsum of spacing (sequential f32 adds)
    float cl  = 0.0f;  // cumsum of log d
    int nact = 0;
    for (int o = 0; o < NOCT; o++) {
        fac = __fadd_rn(fac, sp);
        cl  = __fadd_rn(cl, ld);
        float f0s = __fmul_rn(fsc, fac);
        g_f0s[be * NOCT + o] = f0s;
        g_amp[be * NOCT + o] = expf(cl);
        if (f0s < 1.0f) nact = o + 1;   // mask is a monotone prefix
    }
    g_nact[be] = nact;
}

// ---------------------------------------------------------------------------
// Kernel 2: oscillator bank. Each block = (chunk of 1024 samples) x (one be).
// Accurate sin of the f32-rounded phase via exact 2-FMA Cody-Waite 2*pi
// reduction + MUFU sin on |r| <= pi.
// ---------------------------------------------------------------------------
__global__ void __launch_bounds__(TPB) osc_kernel(float* __restrict__ out) {
    const int be    = blockIdx.y;
    const int chunk = blockIdx.x;
    const int nact  = g_nact[be];

    __shared__ float sf[NOCT];
    __shared__ float sa[NOCT];
    if (threadIdx.x < NOCT) {
        sf[threadIdx.x] = g_f0s[be * NOCT + threadIdx.x];
        sa[threadIdx.x] = g_amp[be * NOCT + threadIdx.x];
    }
    __syncthreads();

    const int base = chunk * SAMP_PER_BLK + threadIdx.x;
    // t = sample_index + 1 (exact small integers in f32)
    const float t0 = (float)(base + 1);
    const float t1 = t0 + 256.0f;
    const float t2 = t0 + 512.0f;
    const float t3 = t0 + 768.0f;

    constexpr double TWO_PI_D = 6.283185307179586476925286766559;
    const float INV2PI = (float)(1.0 / TWO_PI_D);
    const float HI = (float)TWO_PI_D;                       // 6.2831855f
    const float LO = (float)(TWO_PI_D - (double)((float)TWO_PI_D));

    float acc0 = 0.0f, acc1 = 0.0f, acc2 = 0.0f, acc3 = 0.0f;

    for (int o = 0; o < nact; o++) {
        const float f = sf[o];
        const float a = sa[o];

        float p0 = __fmul_rn(f, t0);
        float p1 = __fmul_rn(f, t1);
        float p2 = __fmul_rn(f, t2);
        float p3 = __fmul_rn(f, t3);

        float k0 = rintf(p0 * INV2PI);
        float k1 = rintf(p1 * INV2PI);
        float k2 = rintf(p2 * INV2PI);
        float k3 = rintf(p3 * INV2PI);

        float r0 = fmaf(k0, -HI, p0); r0 = fmaf(k0, -LO, r0);
        float r1 = fmaf(k1, -HI, p1); r1 = fmaf(k1, -LO, r1);
        float r2 = fmaf(k2, -HI, p2); r2 = fmaf(k2, -LO, r2);
        float r3 = fmaf(k3, -HI, p3); r3 = fmaf(k3, -LO, r3);

        acc0 = fmaf(__sinf(r0), a, acc0);
        acc1 = fmaf(__sinf(r1), a, acc1);
        acc2 = fmaf(__sinf(r2), a, acc2);
        acc3 = fmaf(__sinf(r3), a, acc3);
    }

    const int idx = be * NSAMP + base;
    out[idx        ] = acc0;
    out[idx + 256  ] = acc1;
    out[idx + 512  ] = acc2;
    out[idx + 768  ] = acc3;

    // block max-abs reduction -> one atomic per block
    float m = fmaxf(fmaxf(fabsf(acc0), fabsf(acc1)),
                    fmaxf(fabsf(acc2), fabsf(acc3)));
    #pragma unroll
    for (int off = 16; off > 0; off >>= 1)
        m = fmaxf(m, __shfl_xor_sync(0xFFFFFFFFu, m, off));

    __shared__ float wm[TPB / 32];
    if ((threadIdx.x & 31) == 0) wm[threadIdx.x >> 5] = m;
    __syncthreads();
    if (threadIdx.x < (TPB / 32)) {
        float mm = wm[threadIdx.x];
        #pragma unroll
        for (int off = (TPB / 64); off > 0; off >>= 1)
            mm = fmaxf(mm, __shfl_xor_sync(0xFFu, mm, off));
        if (threadIdx.x == 0)
            atomicMax(&g_max[be], __float_as_uint(mm));  // nonneg floats order as uints
    }
}

// ---------------------------------------------------------------------------
// Kernel 3: normalize in place, float4 streaming.
// ---------------------------------------------------------------------------
__global__ void norm_kernel(float4* __restrict__ out) {
    int i = blockIdx.x * blockDim.x + threadIdx.x;       // over 524288 float4
    if (i >= BE * NSAMP / 4) return;
    int be = i >> 13;                                    // 8192 float4 per be
    float mx  = __uint_as_float(g_max[be]);
    float inv = 1.0f / (mx + 1e-8f);
    float4 v = out[i];
    v.x *= inv; v.y *= inv; v.z *= inv; v.w *= inv;
    out[i] = v;
}

extern "C" void kernel_launch(void* const* d_in, const int* in_sizes, int n_in,
                              void* d_out, int out_size) {
    const float* f0  = (const float*)d_in[0];
    const float* dec = (const float*)d_in[1];
    const float* sp  = (const float*)d_in[2];
    float* out = (float*)d_out;

    setup_kernel<<<1, 64>>>(f0, dec, sp);
    dim3 grid(NCHUNK, BE);
    osc_kernel<<<grid, TPB>>>(out);
    norm_kernel<<<(BE * NSAMP / 4 + 255) / 256, 256>>>((float4*)out);
}